// round 16
// baseline (speedup 1.0000x reference)
#include <cuda_runtime.h>
#include <cuda_fp16.h>
#include <math.h>
#include <stdint.h>

// Problem constants
#define BB 2
#define SS 2048
#define TT 2048
#define DIN 2048
#define DOUT 2048
#define HH 16
#define RD 64
#define HALF_RD 32
#define LL 512
#define HD 128
#define ROWS (BB*SS)          // 4096
#define QW (DOUT+HH*RD)       // 3072
#define NROWS ((long)BB*HH*SS)  // 65536 attention rows

// ---------------- device scratch (static; no allocations) ---------------------
__device__ __align__(128) __half g_x16  [ROWS*DIN];
__device__ __align__(128) __half g_wdkv16[LL*DIN];
__device__ __align__(128) __half g_wkr16 [HH*RD*DIN];
__device__ __align__(128) __half g_wq16  [QW*DIN];
__device__ __align__(128) __half g_wo16  [DIN*DOUT];
__device__ __align__(128) __half g_wuv16 [DOUT*LL];
__device__ __align__(128) __half g_wuk16 [DOUT*LL];
__device__ __align__(128) __half g_ckv16 [BB*SS*LL];
__device__ __align__(128) __half g_vt16  [(long)BB*DOUT*SS];    // [b][i, t]
__device__ __align__(128) __half g_krope16[BB*SS*HH*RD];
__device__ __align__(128) __half g_q16   [BB*SS*QW];
__device__ __align__(128) __half g_m2t16 [(long)BB*HH*TT*HD];   // [b,h][t,d]
__device__ __align__(128) __half g_scores16[(long)BB*HH*SS*TT];
__device__ __align__(128) float2 g_part  [NROWS*16];            // per-block (max,sumexp)
__device__ __align__(128) float  g_rowm  [NROWS];
__device__ __align__(128) float  g_rowinv[NROWS];
__device__ __align__(128) __half g_ctx16 [ROWS*DOUT];

// ================= helpers =====================================================
__device__ __forceinline__ uint32_t smem_u32(const void* p) {
    uint32_t a;
    asm("{ .reg .u64 t; cvta.to.shared.u64 t, %1; cvt.u32.u64 %0, t; }" : "=r"(a) : "l"(p));
    return a;
}
__device__ __forceinline__ void cp16(uint32_t dst, const void* src) {
    asm volatile("cp.async.cg.shared.global [%0], [%1], 16;" :: "r"(dst), "l"(src));
}
#define CP_COMMIT() asm volatile("cp.async.commit_group;" ::: "memory")
#define CP_WAIT1()  asm volatile("cp.async.wait_group 1;"  ::: "memory")
#define CP_WAIT0()  asm volatile("cp.async.wait_group 0;"  ::: "memory")

__device__ __forceinline__ void ldsm4(uint32_t* r, uint32_t addr) {
    asm volatile("ldmatrix.sync.aligned.m8n8.x4.shared.b16 {%0,%1,%2,%3}, [%4];"
                 : "=r"(r[0]), "=r"(r[1]), "=r"(r[2]), "=r"(r[3]) : "r"(addr));
}
__device__ __forceinline__ void mma_f16(float* c, const uint32_t* a, const uint32_t* b) {
    asm volatile(
        "mma.sync.aligned.m16n8k16.row.col.f32.f16.f16.f32 "
        "{%0,%1,%2,%3}, {%4,%5,%6,%7}, {%8,%9}, {%0,%1,%2,%3};"
        : "+f"(c[0]), "+f"(c[1]), "+f"(c[2]), "+f"(c[3])
        : "r"(a[0]), "r"(a[1]), "r"(a[2]), "r"(a[3]), "r"(b[0]), "r"(b[1]));
}

// ================= FP16 GEMM tile engine: 128x128, K-chunk 64, 3 stages =========
#define STGB 36864
#define GEMM_SMEM (3*STGB)      // 110592 B; x2 CTA = 216 KB <= 228 KB

__device__ __forceinline__ void gemm_tiles_h(
    const __half* __restrict__ A, const __half* __restrict__ B,
    int K, int lda, int ldb, float (*acc)[4][4], char* sm)
{
    const int tid  = threadIdx.x;
    const int lane = tid & 31;
    const int wid  = tid >> 5;
    const int wm   = wid >> 2;
    const int wn   = wid & 3;

    const uint32_t sbase = smem_u32(sm);

    const int aRow = wm * 64 + (lane & 7) + ((lane >> 3) & 1) * 8;
    const uint32_t aOff = (uint32_t)(aRow * 72 + ((lane >> 4) & 1) * 8) * 2;
    const int bRow = wn * 32 + (lane & 7) + ((lane >> 4) & 1) * 8;
    const uint32_t bOff = (uint32_t)(bRow * 72 + ((lane >> 3) & 1) * 8) * 2;

    auto issue = [&](int c) {
        const int k0 = c << 6;
        const uint32_t st = sbase + (uint32_t)(c % 3) * STGB;
        #pragma unroll
        for (int i = 0; i < 4; i++) {
            int op = tid + i * 256;
            int row = op >> 3, c8 = (op & 7) * 8;
            uint32_t d = st + (uint32_t)(row * 72 + c8) * 2;
            cp16(d,           A + (long)row * lda + k0 + c8);
            cp16(d + 18432,   B + (long)row * ldb + k0 + c8);
        }
    };

    auto compute = [&](int c) {
        const uint32_t As = sbase + (uint32_t)(c % 3) * STGB;
        const uint32_t Bs = As + 18432;
        #pragma unroll
        for (int ks = 0; ks < 4; ks++) {
            uint32_t ah[4][4], bh[4][2];
            #pragma unroll
            for (int mt = 0; mt < 4; mt++)
                ldsm4(ah[mt], As + aOff + (uint32_t)(mt * 16 * 72 + ks * 16) * 2);
            #pragma unroll
            for (int np = 0; np < 2; np++) {
                uint32_t raw[4];
                ldsm4(raw, Bs + bOff + (uint32_t)(np * 16 * 72 + ks * 16) * 2);
                bh[np * 2][0] = raw[0]; bh[np * 2][1] = raw[1];
                bh[np * 2 + 1][0] = raw[2]; bh[np * 2 + 1][1] = raw[3];
            }
            #pragma unroll
            for (int mt = 0; mt < 4; mt++)
                #pragma unroll
                for (int nt = 0; nt < 4; nt++)
                    mma_f16(acc[mt][nt], ah[mt], bh[nt]);
        }
    };

    const int NC = K >> 6;
    issue(0); CP_COMMIT();
    if (1 < NC) issue(1);
    CP_COMMIT();
    for (int c = 0; c < NC; c++) {
        CP_WAIT1();
        __syncthreads();
        if (c + 2 < NC) issue(c + 2);
        CP_COMMIT();
        compute(c);
    }
    CP_WAIT0();
    __syncthreads();
}

// ======= staged epilogue: acc -> SMEM -> coalesced 16B GMEM stores =============
template<int OUTH>
__device__ __forceinline__ void gemm_epi(
    void* __restrict__ Cv, int ldc, int m0, int n0, float (*acc)[4][4], char* sm)
{
    const int tid  = threadIdx.x;
    const int lane = tid & 31;
    const int wid  = tid >> 5;
    const int gid  = lane >> 2;
    const int tig  = lane & 3;
    const int wm   = wid >> 2;
    const int wn   = wid & 3;

    if (OUTH) {
        __half* ts = (__half*)sm;
        #pragma unroll
        for (int mt = 0; mt < 4; mt++) {
            #pragma unroll
            for (int nt = 0; nt < 4; nt++) {
                int r  = wm * 64 + mt * 16 + gid;
                int cc = wn * 32 + nt * 8 + tig * 2;
                *(__half2*)&ts[r * 136 + cc] =
                    __floats2half2_rn(acc[mt][nt][0], acc[mt][nt][1]);
                *(__half2*)&ts[(r + 8) * 136 + cc] =
                    __floats2half2_rn(acc[mt][nt][2], acc[mt][nt][3]);
            }
        }
        __syncthreads();
        __half* C = (__half*)Cv + (long)m0 * ldc + n0;
        #pragma unroll
        for (int i = 0; i < 8; i++) {
            int idx = tid + i * 256;
            int row = idx >> 4, c16 = idx & 15;
            uint4 v = *(const uint4*)&ts[row * 136 + c16 * 8];
            *(uint4*)&C[(long)row * ldc + c16 * 8] = v;
        }
    } else {
        float* ts = (float*)sm;
        #pragma unroll
        for (int mt = 0; mt < 4; mt++) {
            #pragma unroll
            for (int nt = 0; nt < 4; nt++) {
                int r  = wm * 64 + mt * 16 + gid;
                int cc = wn * 32 + nt * 8 + tig * 2;
                *(float2*)&ts[r * 132 + cc] =
                    make_float2(acc[mt][nt][0], acc[mt][nt][1]);
                *(float2*)&ts[(r + 8) * 132 + cc] =
                    make_float2(acc[mt][nt][2], acc[mt][nt][3]);
            }
        }
        __syncthreads();
        float* C = (float*)Cv + (long)m0 * ldc + n0;
        #pragma unroll
        for (int i = 0; i < 16; i++) {
            int idx = tid + i * 256;
            int row = idx >> 5, c4 = idx & 31;
            uint4 v = *(const uint4*)&ts[row * 132 + c4 * 4];
            *(uint4*)&C[(long)row * ldc + c4 * 4] = v;
        }
    }
    __syncthreads();
}

#define ACC_INIT(acc) { _Pragma("unroll") for (int _m = 0; _m < 4; _m++) \
    _Pragma("unroll") for (int _n = 0; _n < 4; _n++) \
    _Pragma("unroll") for (int _i = 0; _i < 4; _i++) acc[_m][_n][_i] = 0.0f; }

// generic batched fp16 GEMM; kclip limits K causally (128-grain, mult of 64)
template<int OUTH>
__global__ void __launch_bounds__(256, 2)
gemm_h(const __half* __restrict__ Ab, const __half* __restrict__ Bb, void* __restrict__ Cb,
       int K, int lda, int ldb, int ldc,
       int zInner, long sAo, long sAi, long sBo, long sBi, long sCo, long sCi,
       const int* offset_p, int kclip)
{
    extern __shared__ char smc[];
    const int z  = blockIdx.z;
    const int zo = z / zInner, zi = z % zInner;
    const int m0 = blockIdx.y * 128;
    const int n0 = blockIdx.x * 128;
    if (kclip) {
        int lim = m0 + 128 + *offset_p;
        lim = (lim + 127) & ~127;
        if (lim < K) K = lim;
    }
    float acc[4][4][4];
    ACC_INIT(acc);
    gemm_tiles_h(Ab + zo * sAo + zi * sAi + (long)m0 * lda,
                 Bb + zo * sBo + zi * sBi + (long)n0 * ldb,
                 K, lda, ldb, acc, smc);
    if (OUTH)
        gemm_epi<1>((__half*)Cb + zo * sCo + zi * sCi, ldc, m0, n0, acc, smc);
    else
        gemm_epi<0>((float*)Cb + zo * sCo + zi * sCi, ldc, m0, n0, acc, smc);
}

// fused triple projection (half out): ckv 4 | krope 8 | q 24 blocks of 128
__global__ void __launch_bounds__(256, 2)
gemm_proj3(const __half* __restrict__ x,
           const __half* __restrict__ Wdkv, const __half* __restrict__ Wkr,
           const __half* __restrict__ Wq,
           __half* __restrict__ ckv, __half* __restrict__ krope, __half* __restrict__ q)
{
    extern __shared__ char smc[];
    const int bx = blockIdx.x;
    const __half* B; __half* C; int ldc, n0;
    if (bx < 4)       { B = Wdkv; C = ckv;   ldc = LL;       n0 = bx * 128; }
    else if (bx < 12) { B = Wkr;  C = krope; ldc = HH * RD;  n0 = (bx - 4) * 128; }
    else              { B = Wq;   C = q;     ldc = QW;       n0 = (bx - 12) * 128; }
    const int m0 = blockIdx.y * 128;
    float acc[4][4][4];
    ACC_INIT(acc);
    gemm_tiles_h(x + (long)m0 * DIN, B + (long)n0 * DIN, DIN, DIN, DIN, acc, smc);
    gemm_epi<1>(C, ldc, m0, n0, acc, smc);
}

// fused scores: rope (K=64) + absorbed latent (K=128 via M2T), causal skip.
// ALSO emits per-(row, t-block) partial softmax stats (max, sumexp) from SMEM.
__global__ void __launch_bounds__(256, 2)
gemm_scores(const __half* __restrict__ q, const __half* __restrict__ krope,
            const __half* __restrict__ m2t,
            __half* __restrict__ scores, float2* __restrict__ part,
            const int* __restrict__ offset_p)
{
    extern __shared__ char smc[];
    const int m0 = blockIdx.y * 128;
    const int n0 = blockIdx.x * 128;
    const int off = *offset_p;
    if (n0 > m0 + 127 + off) return;
    const int b = blockIdx.z >> 4;
    const int h = blockIdx.z & 15;

    float acc[4][4][4];
    ACC_INIT(acc);

    const __half* A1 = q + (long)b * SS * QW + DOUT + h * RD + (long)m0 * QW;
    const __half* B1 = krope + (long)b * SS * (HH * RD) + h * RD + (long)n0 * (HH * RD);
    gemm_tiles_h(A1, B1, RD, QW, HH * RD, acc, smc);

    const __half* A2 = q + (long)b * SS * QW + h * HD + (long)m0 * QW;
    const __half* B2 = m2t + (long)blockIdx.z * TT * HD + (long)n0 * HD;
    gemm_tiles_h(A2, B2, HD, QW, HD, acc, smc);

    gemm_epi<1>(scores + (long)blockIdx.z * SS * TT, TT, m0, n0, acc, smc);

    // partial softmax stats from the staged tile (still intact in SMEM)
    {
        const __half* ts = (const __half*)smc;
        const float scale = rsqrtf((float)(HD + RD));
        const int tid = threadIdx.x;
        const int r  = tid >> 1;         // 0..127
        const int hf = tid & 1;          // which 64-col half
        const int sg = m0 + r;
        int vcols = sg + off - n0 + 1;   // valid cols in this 128-block
        if (vcols > 128) vcols = 128;
        const int cbeg = hf * 64;
        int cend = vcols < cbeg + 64 ? vcols : cbeg + 64;

        float mloc = -INFINITY;
        for (int c = cbeg; c < cend; c++)
            mloc = fmaxf(mloc, __half2float(ts[r * 136 + c]) * scale);
        float sloc = 0.0f;
        for (int c = cbeg; c < cend; c++)
            sloc += __expf(__half2float(ts[r * 136 + c]) * scale - mloc);

        float m2 = __shfl_xor_sync(0xffffffffu, mloc, 1);
        float s2 = __shfl_xor_sync(0xffffffffu, sloc, 1);
        float m  = fmaxf(mloc, m2);
        float st = 0.0f;
        if (mloc != -INFINITY) st += sloc * __expf(mloc - m);
        if (m2   != -INFINITY) st += s2   * __expf(m2 - m);
        if (hf == 0)
            part[((long)blockIdx.z * SS + sg) * 16 + (n0 >> 7)] = make_float2(m, st);
    }
}

// reduce partials -> per-row max and 1/sum
__global__ void __launch_bounds__(256)
reduce_stats(const float2* __restrict__ part, float* __restrict__ rowm,
             float* __restrict__ rowinv, const int* __restrict__ offset_p)
{
    long row = (long)blockIdx.x * blockDim.x + threadIdx.x;
    if (row >= NROWS) return;
    int s = (int)(row % SS);
    int off = *offset_p;
    int nblk = ((s + off) >> 7) + 1;
    if (nblk > 16) nblk = 16;
    const float2* p = part + row * 16;
    float m = -INFINITY;
    for (int b = 0; b < nblk; b++) m = fmaxf(m, p[b].x);
    float sum = 0.0f;
    for (int b = 0; b < nblk; b++) {
        float2 pb = p[b];
        sum += pb.y * __expf(pb.x - m);
    }
    rowm[row] = m;
    rowinv[row] = 1.0f / sum;
}

// ctx = softmax(scores) @ VT^T — exp applied inline on A-load (no probs buffer).
// grid (1, SS/128, BB*HH). C[b*SS+s, h*HD+d].
__global__ void __launch_bounds__(256, 2)
gemm_ctx_flash(const __half* __restrict__ scores, const __half* __restrict__ vt,
               const float* __restrict__ rowm, const float* __restrict__ rowinv,
               __half* __restrict__ ctx, const int* __restrict__ offset_p)
{
    extern __shared__ char smc[];
    const int z  = blockIdx.z;
    const int b  = z >> 4;
    const int h  = z & 15;
    const int m0 = blockIdx.y * 128;
    const int off = *offset_p;

    int K = TT;
    {
        int lim = m0 + 128 + off;
        lim = (lim + 127) & ~127;
        if (lim < K) K = lim;
    }

    const __half* A = scores + (long)z * SS * TT + (long)m0 * TT;   // lda TT
    const __half* B = vt + (long)b * DOUT * SS + (long)(h * HD) * SS; // ldb SS
    const float scale = rsqrtf((float)(HD + RD));

    const int tid  = threadIdx.x;
    const int lane = tid & 31;
    const int wid  = tid >> 5;
    const int wm   = wid >> 2;
    const int wn   = wid & 3;

    // per-thread row stats (rows r0, r0+32, r0+64, r0+96)
    const int r0 = tid >> 3;
    float rmv[4], riv[4];
    int   sv[4];
    #pragma unroll
    for (int i = 0; i < 4; i++) {
        int sg = m0 + r0 + i * 32;
        long sr = (long)z * SS + sg;
        rmv[i] = rowm[sr];
        riv[i] = rowinv[sr];
        sv[i]  = sg + off + 1;      // valid count along t
    }

    const uint32_t sbase = smem_u32(smc);
    const int aRow = wm * 64 + (lane & 7) + ((lane >> 3) & 1) * 8;
    const uint32_t aOff = (uint32_t)(aRow * 72 + ((lane >> 4) & 1) * 8) * 2;
    const int bRow = wn * 32 + (lane & 7) + ((lane >> 4) & 1) * 8;
    const uint32_t bOff = (uint32_t)(bRow * 72 + ((lane >> 3) & 1) * 8) * 2;

    float acc[4][4][4];
    ACC_INIT(acc);

    auto issue = [&](int c) {
        const int k0 = c << 6;
        const uint32_t st = sbase + (uint32_t)(c % 3) * STGB;
        #pragma unroll
        for (int i = 0; i < 4; i++) {
            int op = tid + i * 256;
            int row = op >> 3, c8 = (op & 7) * 8;
            uint32_t d = st + (uint32_t)(row * 72 + c8) * 2;
            // B: async
            cp16(d + 18432, B + (long)row * SS + k0 + c8);
            // A: sync load + exp + store (probs materialized in SMEM only)
            uint4 raw = *(const uint4*)(A + (long)row * TT + k0 + c8);
            const __half* rh = (const __half*)&raw;
            const float rm = rmv[i], ri = riv[i];
            const int tmax = sv[i] - (k0 + c8);
            uint32_t o[4];
            #pragma unroll
            for (int j = 0; j < 4; j++) {
                float v0 = (2 * j < tmax)
                    ? __expf(__half2float(rh[2 * j]) * scale - rm) * ri : 0.0f;
                float v1 = (2 * j + 1 < tmax)
                    ? __expf(__half2float(rh[2 * j + 1]) * scale - rm) * ri : 0.0f;
                __half2 hv = __floats2half2_rn(v0, v1);
                o[j] = *(uint32_t*)&hv;
            }
            asm volatile("st.shared.v4.b32 [%0], {%1,%2,%3,%4};"
                         :: "r"(d), "r"(o[0]), "r"(o[1]), "r"(o[2]), "r"(o[3])
                         : "memory");
        }
    };

    auto compute = [&](int c) {
        const uint32_t As = sbase + (uint32_t)(c % 3) * STGB;
        const uint32_t Bs = As + 18432;
        #pragma unroll
        for (int ks = 0; ks < 4; ks++) {
            uint32_t ah[4][4], bh[4][2];
            #pragma unroll
            for (int mt = 0; mt < 4; mt++)
                ldsm4(ah[mt], As + aOff + (uint32_t)(mt * 16 * 72 + ks * 16) * 2);
            #pragma unroll
            for (int np = 0; np < 2; np++) {
                uint32_t raw[4];
                ldsm4(raw, Bs + bOff + (uint32_t)(np * 16 * 72 + ks * 16) * 2);
                bh[np * 2][0] = raw[0]; bh[np * 2][1] = raw[1];
                bh[np * 2 + 1][0] = raw[2]; bh[np * 2 + 1][1] = raw[3];
            }
            #pragma unroll
            for (int mt = 0; mt < 4; mt++)
                #pragma unroll
                for (int nt = 0; nt < 4; nt++)
                    mma_f16(acc[mt][nt], ah[mt], bh[nt]);
        }
    };

    const int NC = K >> 6;
    issue(0); CP_COMMIT();
    if (1 < NC) issue(1);
    CP_COMMIT();
    for (int c = 0; c < NC; c++) {
        CP_WAIT1();
        __syncthreads();
        if (c + 2 < NC) issue(c + 2);
        CP_COMMIT();
        compute(c);
    }
    CP_WAIT0();
    __syncthreads();

    gemm_epi<1>(ctx + (long)(b * SS) * DOUT + h * HD, DOUT, m0, 0, acc, smc);
}

// ================= small kernels ===============================================
__global__ void halfify_all(
    const float* s0, __half* d0, int n0,
    const float* s1, __half* d1, int n1,
    const float* s2, __half* d2, int n2,
    const float* s3, __half* d3, int n3,
    const float* s4, __half* d4, int n4,
    const float* s5, __half* d5, int n5,
    const float* s6, __half* d6, int n6)
{
    long i = (long)blockIdx.x * blockDim.x + threadIdx.x;
    const float* s; __half* d;
    if (i < n0)              { s = s0; d = d0; }
    else if ((i -= n0) < n1) { s = s1; d = d1; }
    else if ((i -= n1) < n2) { s = s2; d = d2; }
    else if ((i -= n2) < n3) { s = s3; d = d3; }
    else if ((i -= n3) < n4) { s = s4; d = d4; }
    else if ((i -= n4) < n5) { s = s5; d = d5; }
    else if ((i -= n5) < n6) { s = s6; d = d6; }
    else return;
    float4 v = ((const float4*)s)[i];
    __half2* o = (__half2*)d;
    o[i * 2]     = __floats2half2_rn(v.x, v.y);
    o[i * 2 + 1] = __floats2half2_rn(v.z, v.w);
}

__global__ void rmsnorm_kernel(__half* __restrict__ data, const float* __restrict__ w)
{
    const int row = blockIdx.x;
    __half* p = data + (long)row * LL;
    float ss = 0.0f;
    float vals[4];
    #pragma unroll
    for (int i = 0; i < 4; i++) {
        vals[i] = __half2float(p[threadIdx.x + i * 128]);
        ss += vals[i] * vals[i];
    }
    __shared__ float red[32];
    for (int o = 16; o; o >>= 1) ss += __shfl_xor_sync(0xffffffffu, ss, o);
    if ((threadIdx.x & 31) == 0) red[threadIdx.x >> 5] = ss;
    __syncthreads();
    if (threadIdx.x < 32) {
        float v = (threadIdx.x < 4) ? red[threadIdx.x] : 0.0f;
        for (int o = 16; o; o >>= 1) v += __shfl_xor_sync(0xffffffffu, v, o);
        if (threadIdx.x == 0) red[0] = v;
    }
    __syncthreads();
    float rstd = rsqrtf(red[0] / (float)LL + 1e-6f);
    #pragma unroll
    for (int i = 0; i < 4; i++)
        p[threadIdx.x + i * 128] = __float2half_rn(vals[i] * rstd * w[threadIdx.x + i * 128]);
}

// both rope applications in one launch
__global__ void rope_both(__half* __restrict__ krope, __half* __restrict__ q,
                          const int* __restrict__ offset_p)
{
    const long per = (long)ROWS * HH * HALF_RD;
    long idx = (long)blockIdx.x * blockDim.x + threadIdx.x;
    __half* data; int ld, colbase;
    if (idx < per) { data = krope; ld = HH * RD; colbase = 0; }
    else if ((idx -= per) < per) { data = q; ld = QW; colbase = DOUT; }
    else return;
    int  j   = (int)(idx % HALF_RD);
    int  h   = (int)((idx / HALF_RD) % HH);
    long row = idx / (HALF_RD * HH);
    int  s   = (int)(row % SS);
    float pos = (float)(s + *offset_p);
    float inv = expf(-(float)j * (logf(10000.0f) / 32.0f));
    float ang = pos * inv;
    float c  = cosf(ang);
    float si = sinf(ang);
    __half* p = data + row * (long)ld + colbase + h * RD;
    float x1 = __half2float(p[j]), x2 = __half2float(p[j + HALF_RD]);
    p[j]           = __float2half_rn(x1 * c - x2 * si);
    p[j + HALF_RD] = __float2half_rn(x2 * c + x1 * si);
}

// ================= host side ====================================================
template<typename T>
static T* sym_addr(const void* sym)
{
    void* p = nullptr;
    cudaGetSymbolAddress(&p, sym);
    return (T*)p;
}

extern "C" void kernel_launch(void* const* d_in, const int* in_sizes, int n_in,
                              void* d_out, int out_size)
{
    const float* x       = (const float*)d_in[0];
    const float* W_DKV   = (const float*)d_in[1];
    const float* W_KRope = (const float*)d_in[2];
    const float* W_Q     = (const float*)d_in[3];
    const float* W_UK    = (const float*)d_in[4];
    const float* W_UV    = (const float*)d_in[5];
    const float* W_O     = (const float*)d_in[6];
    const float* kvw     = (const float*)d_in[7];
    const int*   offset  = (const int*)d_in[8];
    float* out = (float*)d_out;

    static int s_init = 0;
    if (!s_init) {
        cudaFuncSetAttribute((const void*)gemm_h<0>, cudaFuncAttributeMaxDynamicSharedMemorySize, GEMM_SMEM);
        cudaFuncSetAttribute((const void*)gemm_h<1>, cudaFuncAttributeMaxDynamicSharedMemorySize, GEMM_SMEM);
        cudaFuncSetAttribute((const void*)gemm_proj3, cudaFuncAttributeMaxDynamicSharedMemorySize, GEMM_SMEM);
        cudaFuncSetAttribute((const void*)gemm_scores, cudaFuncAttributeMaxDynamicSharedMemorySize, GEMM_SMEM);
        cudaFuncSetAttribute((const void*)gemm_ctx_flash, cudaFuncAttributeMaxDynamicSharedMemorySize, GEMM_SMEM);
        s_init = 1;
    }

    __half* x16    = sym_addr<__half>(g_x16);
    __half* wdkv16 = sym_addr<__half>(g_wdkv16);
    __half* wkr16  = sym_addr<__half>(g_wkr16);
    __half* wq16   = sym_addr<__half>(g_wq16);
    __half* wo16   = sym_addr<__half>(g_wo16);
    __half* wuv16  = sym_addr<__half>(g_wuv16);
    __half* wuk16  = sym_addr<__half>(g_wuk16);
    __half* ckv16  = sym_addr<__half>(g_ckv16);
    __half* vt16   = sym_addr<__half>(g_vt16);
    __half* krope16= sym_addr<__half>(g_krope16);
    __half* q16    = sym_addr<__half>(g_q16);
    __half* m2t16  = sym_addr<__half>(g_m2t16);
    __half* scores16 = sym_addr<__half>(g_scores16);
    float2* part   = sym_addr<float2>(g_part);
    float*  rowm   = sym_addr<float>(g_rowm);
    float*  rowinv = sym_addr<float>(g_rowinv);
    __half* ctx16  = sym_addr<__half>(g_ctx16);

    // 0) half-round all seven fp32 inputs in ONE launch
    {
        const int nx = ROWS*DIN/4, n1 = LL*DIN/4, n2 = HH*RD*DIN/4;
        const int n3 = QW*DIN/4, n4 = DIN*DOUT/4, n5 = DOUT*LL/4, n6 = DOUT*LL/4;
        long total = (long)nx + n1 + n2 + n3 + n4 + n5 + n6;
        halfify_all<<<(int)((total + 255) / 256), 256>>>(
            x, x16, nx, W_DKV, wdkv16, n1, W_KRope, wkr16, n2,
            W_Q, wq16, n3, W_O, wo16, n4, W_UV, wuv16, n5, W_UK, wuk16, n6);
    }

    // 1-3) fused projections
    {
        dim3 grid(36, 32, 1);
        gemm_proj3<<<grid, 256, GEMM_SMEM>>>(x16, wdkv16, wkr16, wq16,
                                             ckv16, krope16, q16);
    }
    rmsnorm_kernel<<<ROWS, 128>>>(ckv16, kvw);
    {
        long total = 2L * ROWS * HH * HALF_RD;
        rope_both<<<(int)((total + 255) / 256), 256>>>(krope16, q16, offset);
    }

    // 4a) M2T[b,h][t,d] = ckv[b][t,:] . W_UK[h][d,:]   (K=512)
    {
        dim3 grid(HD / 128, TT / 128, BB * HH);
        gemm_h<1><<<grid, 256, GEMM_SMEM>>>(ckv16, wuk16, m2t16,
            LL, LL, LL, HD,
            HH,
            (long)SS * LL, 0,
            0, (long)HD * LL,
            (long)HH * TT * HD, (long)TT * HD,
            nullptr, 0);
    }

    // 4b) VT[b][i,t] = W_UV[i,:] . ckv[b][t,:]   (K=512)
    {
        dim3 grid(SS / 128, DOUT / 128, BB);
        gemm_h<1><<<grid, 256, GEMM_SMEM>>>(wuv16, ckv16, vt16,
            LL, LL, LL, SS,
            1,
            0, 0,
            (long)SS * LL, 0,
            (long)DOUT * SS, 0,
            nullptr, 0);
    }

    // 5) fused scores + per-block softmax partials (causal skip)
    {
        dim3 grid(TT / 128, SS / 128, BB * HH);
        gemm_scores<<<grid, 256, GEMM_SMEM>>>(q16, krope16, m2t16,
                                              scores16, part, offset);
    }

    // 6) reduce partials -> per-row max, 1/sum
    reduce_stats<<<(int)((NROWS + 255) / 256), 256>>>(part, rowm, rowinv, offset);

    // 7) ctx = softmax(scores) @ VT^T (exp inline, K clipped causally)
    {
        dim3 grid(1, SS / 128, BB * HH);
        gemm_ctx_flash<<<grid, 256, GEMM_SMEM>>>(scores16, vt16, rowm, rowinv,
                                                 ctx16, offset);
    }

    // 8) out = ctx @ W_O^T (fp32 out, staged coalesced)
    {
        dim3 grid(DIN / 128, ROWS / 128, 1);
        gemm_h<0><<<grid, 256, GEMM_SMEM>>>(ctx16, wo16, out,
            DOUT, DOUT, DOUT, DIN,
            1, 0, 0, 0, 0, 0, 0, nullptr, 0);
    }
}

// round 17
// speedup vs baseline: 1.0279x; 1.0279x over previous
#include <cuda_runtime.h>
#include <cuda_fp16.h>
#include <math.h>
#include <stdint.h>

// Problem constants
#define BB 2
#define SS 2048
#define TT 2048
#define DIN 2048
#define DOUT 2048
#define HH 16
#define RD 64
#define HALF_RD 32
#define LL 512
#define HD 128
#define ROWS (BB*SS)          // 4096
#define QW (DOUT+HH*RD)       // 3072

// ---------------- device scratch (static; no allocations) ---------------------
__device__ __align__(128) __half g_x16  [ROWS*DIN];
__device__ __align__(128) __half g_wdkv16[LL*DIN];
__device__ __align__(128) __half g_wkr16 [HH*RD*DIN];
__device__ __align__(128) __half g_wq16  [QW*DIN];
__device__ __align__(128) __half g_wo16  [DIN*DOUT];
__device__ __align__(128) __half g_wuv16 [DOUT*LL];
__device__ __align__(128) __half g_wuk16 [DOUT*LL];
__device__ __align__(128) __half g_ckv16 [BB*SS*LL];
__device__ __align__(128) __half g_vt16  [(long)BB*DOUT*SS];    // [b][i, t]
__device__ __align__(128) __half g_krope16[BB*SS*HH*RD];
__device__ __align__(128) __half g_q16   [BB*SS*QW];
__device__ __align__(128) __half g_m2t16 [(long)BB*HH*TT*HD];   // [b,h][t,d]
__device__ __align__(128) __half g_scores16[(long)BB*HH*SS*TT];
__device__ __align__(128) __half g_probs16 [(long)BB*HH*SS*TT];
__device__ __align__(128) __half g_ctx16 [ROWS*DOUT];

// ================= helpers =====================================================
__device__ __forceinline__ uint32_t smem_u32(const void* p) {
    uint32_t a;
    asm("{ .reg .u64 t; cvta.to.shared.u64 t, %1; cvt.u32.u64 %0, t; }" : "=r"(a) : "l"(p));
    return a;
}
__device__ __forceinline__ void cp16(uint32_t dst, const void* src) {
    asm volatile("cp.async.cg.shared.global [%0], [%1], 16;" :: "r"(dst), "l"(src));
}
#define CP_COMMIT() asm volatile("cp.async.commit_group;" ::: "memory")
#define CP_WAIT1()  asm volatile("cp.async.wait_group 1;"  ::: "memory")
#define CP_WAIT0()  asm volatile("cp.async.wait_group 0;"  ::: "memory")

__device__ __forceinline__ void ldsm4(uint32_t* r, uint32_t addr) {
    asm volatile("ldmatrix.sync.aligned.m8n8.x4.shared.b16 {%0,%1,%2,%3}, [%4];"
                 : "=r"(r[0]), "=r"(r[1]), "=r"(r[2]), "=r"(r[3]) : "r"(addr));
}
__device__ __forceinline__ void mma_f16(float* c, const uint32_t* a, const uint32_t* b) {
    asm volatile(
        "mma.sync.aligned.m16n8k16.row.col.f32.f16.f16.f32 "
        "{%0,%1,%2,%3}, {%4,%5,%6,%7}, {%8,%9}, {%0,%1,%2,%3};"
        : "+f"(c[0]), "+f"(c[1]), "+f"(c[2]), "+f"(c[3])
        : "r"(a[0]), "r"(a[1]), "r"(a[2]), "r"(a[3]), "r"(b[0]), "r"(b[1]));
}

// ================= FP16 GEMM tile engine: 128x128, K-chunk 64, 3 stages =========
#define STGB 36864
#define GEMM_SMEM (3*STGB)      // 110592 B; x2 CTA = 216 KB <= 228 KB

__device__ __forceinline__ void gemm_tiles_h(
    const __half* __restrict__ A, const __half* __restrict__ B,
    int K, int lda, int ldb, float (*acc)[4][4], char* sm)
{
    const int tid  = threadIdx.x;
    const int lane = tid & 31;
    const int wid  = tid >> 5;
    const int wm   = wid >> 2;
    const int wn   = wid & 3;

    const uint32_t sbase = smem_u32(sm);

    const int aRow = wm * 64 + (lane & 7) + ((lane >> 3) & 1) * 8;
    const uint32_t aOff = (uint32_t)(aRow * 72 + ((lane >> 4) & 1) * 8) * 2;
    const int bRow = wn * 32 + (lane & 7) + ((lane >> 4) & 1) * 8;
    const uint32_t bOff = (uint32_t)(bRow * 72 + ((lane >> 3) & 1) * 8) * 2;

    auto issue = [&](int c) {
        const int k0 = c << 6;
        const uint32_t st = sbase + (uint32_t)(c % 3) * STGB;
        #pragma unroll
        for (int i = 0; i < 4; i++) {
            int op = tid + i * 256;
            int row = op >> 3, c8 = (op & 7) * 8;
            uint32_t d = st + (uint32_t)(row * 72 + c8) * 2;
            cp16(d,           A + (long)row * lda + k0 + c8);
            cp16(d + 18432,   B + (long)row * ldb + k0 + c8);
        }
    };

    auto compute = [&](int c) {
        const uint32_t As = sbase + (uint32_t)(c % 3) * STGB;
        const uint32_t Bs = As + 18432;
        #pragma unroll
        for (int ks = 0; ks < 4; ks++) {
            uint32_t ah[4][4], bh[4][2];
            #pragma unroll
            for (int mt = 0; mt < 4; mt++)
                ldsm4(ah[mt], As + aOff + (uint32_t)(mt * 16 * 72 + ks * 16) * 2);
            #pragma unroll
            for (int np = 0; np < 2; np++) {
                uint32_t raw[4];
                ldsm4(raw, Bs + bOff + (uint32_t)(np * 16 * 72 + ks * 16) * 2);
                bh[np * 2][0] = raw[0]; bh[np * 2][1] = raw[1];
                bh[np * 2 + 1][0] = raw[2]; bh[np * 2 + 1][1] = raw[3];
            }
            #pragma unroll
            for (int mt = 0; mt < 4; mt++)
                #pragma unroll
                for (int nt = 0; nt < 4; nt++)
                    mma_f16(acc[mt][nt], ah[mt], bh[nt]);
        }
    };

    const int NC = K >> 6;
    issue(0); CP_COMMIT();
    if (1 < NC) issue(1);
    CP_COMMIT();
    for (int c = 0; c < NC; c++) {
        CP_WAIT1();
        __syncthreads();
        if (c + 2 < NC) issue(c + 2);
        CP_COMMIT();
        compute(c);
    }
    CP_WAIT0();
    __syncthreads();
}

// ======= staged epilogue: acc -> SMEM -> coalesced 16B GMEM stores =============
template<int OUTH>
__device__ __forceinline__ void gemm_epi(
    void* __restrict__ Cv, int ldc, int m0, int n0, float (*acc)[4][4], char* sm)
{
    const int tid  = threadIdx.x;
    const int lane = tid & 31;
    const int wid  = tid >> 5;
    const int gid  = lane >> 2;
    const int tig  = lane & 3;
    const int wm   = wid >> 2;
    const int wn   = wid & 3;

    if (OUTH) {
        __half* ts = (__half*)sm;
        #pragma unroll
        for (int mt = 0; mt < 4; mt++) {
            #pragma unroll
            for (int nt = 0; nt < 4; nt++) {
                int r  = wm * 64 + mt * 16 + gid;
                int cc = wn * 32 + nt * 8 + tig * 2;
                *(__half2*)&ts[r * 136 + cc] =
                    __floats2half2_rn(acc[mt][nt][0], acc[mt][nt][1]);
                *(__half2*)&ts[(r + 8) * 136 + cc] =
                    __floats2half2_rn(acc[mt][nt][2], acc[mt][nt][3]);
            }
        }
        __syncthreads();
        __half* C = (__half*)Cv + (long)m0 * ldc + n0;
        #pragma unroll
        for (int i = 0; i < 8; i++) {
            int idx = tid + i * 256;
            int row = idx >> 4, c16 = idx & 15;
            uint4 v = *(const uint4*)&ts[row * 136 + c16 * 8];
            *(uint4*)&C[(long)row * ldc + c16 * 8] = v;
        }
    } else {
        float* ts = (float*)sm;
        #pragma unroll
        for (int mt = 0; mt < 4; mt++) {
            #pragma unroll
            for (int nt = 0; nt < 4; nt++) {
                int r  = wm * 64 + mt * 16 + gid;
                int cc = wn * 32 + nt * 8 + tig * 2;
                *(float2*)&ts[r * 132 + cc] =
                    make_float2(acc[mt][nt][0], acc[mt][nt][1]);
                *(float2*)&ts[(r + 8) * 132 + cc] =
                    make_float2(acc[mt][nt][2], acc[mt][nt][3]);
            }
        }
        __syncthreads();
        float* C = (float*)Cv + (long)m0 * ldc + n0;
        #pragma unroll
        for (int i = 0; i < 16; i++) {
            int idx = tid + i * 256;
            int row = idx >> 5, c4 = idx & 31;
            uint4 v = *(const uint4*)&ts[row * 132 + c4 * 4];
            *(uint4*)&C[(long)row * ldc + c4 * 4] = v;
        }
    }
    __syncthreads();
}

#define ACC_INIT(acc) { _Pragma("unroll") for (int _m = 0; _m < 4; _m++) \
    _Pragma("unroll") for (int _n = 0; _n < 4; _n++) \
    _Pragma("unroll") for (int _i = 0; _i < 4; _i++) acc[_m][_n][_i] = 0.0f; }

// generic batched fp16 GEMM; kclip limits K causally (128-grain, mult of 64)
template<int OUTH>
__global__ void __launch_bounds__(256, 2)
gemm_h(const __half* __restrict__ Ab, const __half* __restrict__ Bb, void* __restrict__ Cb,
       int K, int lda, int ldb, int ldc,
       int zInner, long sAo, long sAi, long sBo, long sBi, long sCo, long sCi,
       const int* offset_p, int kclip)
{
    extern __shared__ char smc[];
    const int z  = blockIdx.z;
    const int zo = z / zInner, zi = z % zInner;
    const int m0 = blockIdx.y * 128;
    const int n0 = blockIdx.x * 128;
    if (kclip) {
        int lim = m0 + 128 + *offset_p;
        lim = (lim + 127) & ~127;
        if (lim < K) K = lim;
    }
    float acc[4][4][4];
    ACC_INIT(acc);
    gemm_tiles_h(Ab + zo * sAo + zi * sAi + (long)m0 * lda,
                 Bb + zo * sBo + zi * sBi + (long)n0 * ldb,
                 K, lda, ldb, acc, smc);
    if (OUTH)
        gemm_epi<1>((__half*)Cb + zo * sCo + zi * sCi, ldc, m0, n0, acc, smc);
    else
        gemm_epi<0>((float*)Cb + zo * sCo + zi * sCi, ldc, m0, n0, acc, smc);
}

// fused triple projection (half out): ckv 4 | krope 8 | q 24 blocks of 128
__global__ void __launch_bounds__(256, 2)
gemm_proj3(const __half* __restrict__ x,
           const __half* __restrict__ Wdkv, const __half* __restrict__ Wkr,
           const __half* __restrict__ Wq,
           __half* __restrict__ ckv, __half* __restrict__ krope, __half* __restrict__ q)
{
    extern __shared__ char smc[];
    const int bx = blockIdx.x;
    const __half* B; __half* C; int ldc, n0;
    if (bx < 4)       { B = Wdkv; C = ckv;   ldc = LL;       n0 = bx * 128; }
    else if (bx < 12) { B = Wkr;  C = krope; ldc = HH * RD;  n0 = (bx - 4) * 128; }
    else              { B = Wq;   C = q;     ldc = QW;       n0 = (bx - 12) * 128; }
    const int m0 = blockIdx.y * 128;
    float acc[4][4][4];
    ACC_INIT(acc);
    gemm_tiles_h(x + (long)m0 * DIN, B + (long)n0 * DIN, DIN, DIN, DIN, acc, smc);
    gemm_epi<1>(C, ldc, m0, n0, acc, smc);
}

// fused scores: rope (K=64) + absorbed latent (K=128 via M2T), causal skip
__global__ void __launch_bounds__(256, 2)
gemm_scores(const __half* __restrict__ q, const __half* __restrict__ krope,
            const __half* __restrict__ m2t,
            __half* __restrict__ scores, const int* __restrict__ offset_p)
{
    extern __shared__ char smc[];
    const int m0 = blockIdx.y * 128;
    const int n0 = blockIdx.x * 128;
    if (n0 > m0 + 127 + *offset_p) return;
    const int b = blockIdx.z >> 4;
    const int h = blockIdx.z & 15;

    float acc[4][4][4];
    ACC_INIT(acc);

    const __half* A1 = q + (long)b * SS * QW + DOUT + h * RD + (long)m0 * QW;
    const __half* B1 = krope + (long)b * SS * (HH * RD) + h * RD + (long)n0 * (HH * RD);
    gemm_tiles_h(A1, B1, RD, QW, HH * RD, acc, smc);

    const __half* A2 = q + (long)b * SS * QW + h * HD + (long)m0 * QW;
    const __half* B2 = m2t + (long)blockIdx.z * TT * HD + (long)n0 * HD;
    gemm_tiles_h(A2, B2, HD, QW, HD, acc, smc);

    gemm_epi<1>(scores + (long)blockIdx.z * SS * TT, TT, m0, n0, acc, smc);
}

// ================= small kernels ===============================================
// one kernel, seven fp32->fp16 segments (float4 granularity)
__global__ void halfify_all(
    const float* s0, __half* d0, int n0,
    const float* s1, __half* d1, int n1,
    const float* s2, __half* d2, int n2,
    const float* s3, __half* d3, int n3,
    const float* s4, __half* d4, int n4,
    const float* s5, __half* d5, int n5,
    const float* s6, __half* d6, int n6)
{
    long i = (long)blockIdx.x * blockDim.x + threadIdx.x;
    const float* s; __half* d;
    if (i < n0)              { s = s0; d = d0; }
    else if ((i -= n0) < n1) { s = s1; d = d1; }
    else if ((i -= n1) < n2) { s = s2; d = d2; }
    else if ((i -= n2) < n3) { s = s3; d = d3; }
    else if ((i -= n3) < n4) { s = s4; d = d4; }
    else if ((i -= n4) < n5) { s = s5; d = d5; }
    else if ((i -= n5) < n6) { s = s6; d = d6; }
    else return;
    float4 v = ((const float4*)s)[i];
    __half2* o = (__half2*)d;
    o[i * 2]     = __floats2half2_rn(v.x, v.y);
    o[i * 2 + 1] = __floats2half2_rn(v.z, v.w);
}

__global__ void rmsnorm_kernel(__half* __restrict__ data, const float* __restrict__ w)
{
    const int row = blockIdx.x;
    __half* p = data + (long)row * LL;
    float ss = 0.0f;
    float vals[4];
    #pragma unroll
    for (int i = 0; i < 4; i++) {
        vals[i] = __half2float(p[threadIdx.x + i * 128]);
        ss += vals[i] * vals[i];
    }
    __shared__ float red[32];
    for (int o = 16; o; o >>= 1) ss += __shfl_xor_sync(0xffffffffu, ss, o);
    if ((threadIdx.x & 31) == 0) red[threadIdx.x >> 5] = ss;
    __syncthreads();
    if (threadIdx.x < 32) {
        float v = (threadIdx.x < 4) ? red[threadIdx.x] : 0.0f;
        for (int o = 16; o; o >>= 1) v += __shfl_xor_sync(0xffffffffu, v, o);
        if (threadIdx.x == 0) red[0] = v;
    }
    __syncthreads();
    float rstd = rsqrtf(red[0] / (float)LL + 1e-6f);
    #pragma unroll
    for (int i = 0; i < 4; i++)
        p[threadIdx.x + i * 128] = __float2half_rn(vals[i] * rstd * w[threadIdx.x + i * 128]);
}

// both rope applications, vectorized: one thread = 2 adjacent j's (half2 pairs)
__global__ void rope_both(__half* __restrict__ krope, __half* __restrict__ q,
                          const int* __restrict__ offset_p)
{
    const long per = (long)ROWS * HH * (HALF_RD / 2);   // pairs
    long idx = (long)blockIdx.x * blockDim.x + threadIdx.x;
    __half* data; int ld, colbase;
    if (idx < per) { data = krope; ld = HH * RD; colbase = 0; }
    else if ((idx -= per) < per) { data = q; ld = QW; colbase = DOUT; }
    else return;
    int  jp  = (int)(idx % (HALF_RD / 2));     // pair index 0..15
    int  h   = (int)((idx / (HALF_RD / 2)) % HH);
    long row = idx / ((HALF_RD / 2) * HH);
    int  s   = (int)(row % SS);
    float pos = (float)(s + *offset_p);
    const float lf = logf(10000.0f) / 32.0f;
    int j0 = jp * 2;
    float ang0 = pos * expf(-(float)j0 * lf);
    float ang1 = pos * expf(-(float)(j0 + 1) * lf);
    float c0 = cosf(ang0), s0 = sinf(ang0);
    float c1 = cosf(ang1), s1 = sinf(ang1);
    __half* p = data + row * (long)ld + colbase + h * RD;
    float2 x1 = __half22float2(*(__half2*)(p + j0));
    float2 x2 = __half22float2(*(__half2*)(p + j0 + HALF_RD));
    *(__half2*)(p + j0) =
        __floats2half2_rn(x1.x * c0 - x2.x * s0, x1.y * c1 - x2.y * s1);
    *(__half2*)(p + j0 + HALF_RD) =
        __floats2half2_rn(x2.x * c0 + x1.x * s0, x2.y * c1 + x1.y * s1);
}

// masked scaled softmax; half scores in, half probs out; zero-fill to 128-grain
__global__ void __launch_bounds__(256)
softmax_kernel(const __half* __restrict__ scores, __half* __restrict__ probs,
               const int* __restrict__ offset_p)
{
    const long row = blockIdx.x;
    const int  s   = (int)(row % SS);
    const int  off = *offset_p;
    int valid = s + off + 1;
    if (valid > TT) valid = TT;
    int limit = ((s & ~127) + 128 + off + 127) & ~127;
    if (limit > TT) limit = TT;
    const __half* p = scores + row * (long)TT;
    __half* op = probs + row * (long)TT;
    const float scale = rsqrtf((float)(HD + RD));
    const int tid = threadIdx.x;
    const int e0 = tid * 8;

    float f[8];
    float m = -INFINITY;
    if (e0 < valid) {
        uint4 raw = *(const uint4*)(p + e0);
        const __half2* hp = (const __half2*)&raw;
        #pragma unroll
        for (int j = 0; j < 4; j++) {
            float2 v2 = __half22float2(hp[j]);
            f[j * 2]     = (e0 + j * 2 < valid)     ? v2.x * scale : -INFINITY;
            f[j * 2 + 1] = (e0 + j * 2 + 1 < valid) ? v2.y * scale : -INFINITY;
        }
        #pragma unroll
        for (int j = 0; j < 8; j++) m = fmaxf(m, f[j]);
    } else {
        #pragma unroll
        for (int j = 0; j < 8; j++) f[j] = -INFINITY;
    }

    __shared__ float red[32];
    for (int o = 16; o; o >>= 1) m = fmaxf(m, __shfl_xor_sync(0xffffffffu, m, o));
    if ((tid & 31) == 0) red[tid >> 5] = m;
    __syncthreads();
    if (tid < 32) {
        float t = (tid < 8) ? red[tid] : -INFINITY;
        for (int o = 16; o; o >>= 1) t = fmaxf(t, __shfl_xor_sync(0xffffffffu, t, o));
        if (tid == 0) red[0] = t;
    }
    __syncthreads();
    m = red[0];
    __syncthreads();

    float sum = 0.0f;
    #pragma unroll
    for (int j = 0; j < 8; j++) {
        float e = (f[j] == -INFINITY) ? 0.0f : expf(f[j] - m);
        f[j] = e;
        sum += e;
    }
    for (int o = 16; o; o >>= 1) sum += __shfl_xor_sync(0xffffffffu, sum, o);
    if ((tid & 31) == 0) red[tid >> 5] = sum;
    __syncthreads();
    if (tid < 32) {
        float t = (tid < 8) ? red[tid] : 0.0f;
        for (int o = 16; o; o >>= 1) t += __shfl_xor_sync(0xffffffffu, t, o);
        if (tid == 0) red[0] = t;
    }
    __syncthreads();
    float inv = 1.0f / red[0];

    if (e0 < limit) {
        uint4 outv;
        __half2* ho = (__half2*)&outv;
        #pragma unroll
        for (int j = 0; j < 4; j++)
            ho[j] = __floats2half2_rn(f[j * 2] * inv, f[j * 2 + 1] * inv);
        *(uint4*)(op + e0) = outv;
    }
}

// ================= host side ====================================================
template<typename T>
static T* sym_addr(const void* sym)
{
    void* p = nullptr;
    cudaGetSymbolAddress(&p, sym);
    return (T*)p;
}

extern "C" void kernel_launch(void* const* d_in, const int* in_sizes, int n_in,
                              void* d_out, int out_size)
{
    const float* x       = (const float*)d_in[0];
    const float* W_DKV   = (const float*)d_in[1];
    const float* W_KRope = (const float*)d_in[2];
    const float* W_Q     = (const float*)d_in[3];
    const float* W_UK    = (const float*)d_in[4];
    const float* W_UV    = (const float*)d_in[5];
    const float* W_O     = (const float*)d_in[6];
    const float* kvw     = (const float*)d_in[7];
    const int*   offset  = (const int*)d_in[8];
    float* out = (float*)d_out;

    static int s_init = 0;
    if (!s_init) {
        cudaFuncSetAttribute((const void*)gemm_h<0>, cudaFuncAttributeMaxDynamicSharedMemorySize, GEMM_SMEM);
        cudaFuncSetAttribute((const void*)gemm_h<1>, cudaFuncAttributeMaxDynamicSharedMemorySize, GEMM_SMEM);
        cudaFuncSetAttribute((const void*)gemm_proj3, cudaFuncAttributeMaxDynamicSharedMemorySize, GEMM_SMEM);
        cudaFuncSetAttribute((const void*)gemm_scores, cudaFuncAttributeMaxDynamicSharedMemorySize, GEMM_SMEM);
        s_init = 1;
    }

    __half* x16    = sym_addr<__half>(g_x16);
    __half* wdkv16 = sym_addr<__half>(g_wdkv16);
    __half* wkr16  = sym_addr<__half>(g_wkr16);
    __half* wq16   = sym_addr<__half>(g_wq16);
    __half* wo16   = sym_addr<__half>(g_wo16);
    __half* wuv16  = sym_addr<__half>(g_wuv16);
    __half* wuk16  = sym_addr<__half>(g_wuk16);
    __half* ckv16  = sym_addr<__half>(g_ckv16);
    __half* vt16   = sym_addr<__half>(g_vt16);
    __half* krope16= sym_addr<__half>(g_krope16);
    __half* q16    = sym_addr<__half>(g_q16);
    __half* m2t16  = sym_addr<__half>(g_m2t16);
    __half* scores16 = sym_addr<__half>(g_scores16);
    __half* probs16  = sym_addr<__half>(g_probs16);
    __half* ctx16  = sym_addr<__half>(g_ctx16);

    // 0) half-round all seven fp32 inputs in ONE launch
    {
        const int nx = ROWS*DIN/4, n1 = LL*DIN/4, n2 = HH*RD*DIN/4;
        const int n3 = QW*DIN/4, n4 = DIN*DOUT/4, n5 = DOUT*LL/4, n6 = DOUT*LL/4;
        long total = (long)nx + n1 + n2 + n3 + n4 + n5 + n6;
        halfify_all<<<(int)((total + 255) / 256), 256>>>(
            x, x16, nx, W_DKV, wdkv16, n1, W_KRope, wkr16, n2,
            W_Q, wq16, n3, W_O, wo16, n4, W_UV, wuv16, n5, W_UK, wuk16, n6);
    }

    // 1-3) fused projections
    {
        dim3 grid(36, 32, 1);
        gemm_proj3<<<grid, 256, GEMM_SMEM>>>(x16, wdkv16, wkr16, wq16,
                                             ckv16, krope16, q16);
    }
    rmsnorm_kernel<<<ROWS, 128>>>(ckv16, kvw);
    {
        long total = 2L * ROWS * HH * (HALF_RD / 2);
        rope_both<<<(int)((total + 255) / 256), 256>>>(krope16, q16, offset);
    }

    // 4a) M2T[b,h][t,d] = ckv[b][t,:] . W_UK[h][d,:]   (K=512)
    {
        dim3 grid(HD / 128, TT / 128, BB * HH);
        gemm_h<1><<<grid, 256, GEMM_SMEM>>>(ckv16, wuk16, m2t16,
            LL, LL, LL, HD,
            HH,
            (long)SS * LL, 0,
            0, (long)HD * LL,
            (long)HH * TT * HD, (long)TT * HD,
            nullptr, 0);
    }

    // 4b) VT[b][i,t] = W_UV[i,:] . ckv[b][t,:]   (K=512)
    {
        dim3 grid(SS / 128, DOUT / 128, BB);
        gemm_h<1><<<grid, 256, GEMM_SMEM>>>(wuv16, ckv16, vt16,
            LL, LL, LL, SS,
            1,
            0, 0,
            (long)SS * LL, 0,
            (long)DOUT * SS, 0,
            nullptr, 0);
    }

    // 5) fused scores: rope(K=64) + q_content @ M2T (K=128), causal skip
    {
        dim3 grid(TT / 128, SS / 128, BB * HH);
        gemm_scores<<<grid, 256, GEMM_SMEM>>>(q16, krope16, m2t16,
                                              scores16, offset);
    }

    // 6) softmax: half scores -> half probs
    softmax_kernel<<<BB * HH * SS, 256>>>(scores16, probs16, offset);

    // 7) ctx = probs @ VT^T per head (K=T clipped causally), half out
    {
        dim3 grid(HD / 128, SS / 128, BB * HH);
        gemm_h<1><<<grid, 256, GEMM_SMEM>>>(probs16, vt16, ctx16,
            TT, TT, SS, DOUT,
            HH,
            (long)HH * SS * TT, (long)SS * TT,
            (long)DOUT * SS, (long)HD * SS,
            (long)SS * DOUT, HD,
            offset, 1);
    }

    // 8) out = ctx @ W_O^T (fp32 out, staged coalesced)
    {
        dim3 grid(DIN / 128, ROWS / 128, 1);
        gemm_h<0><<<grid, 256, GEMM_SMEM>>>(ctx16, wo16, out,
            DOUT, DOUT, DOUT, DIN,
            1, 0, 0, 0, 0, 0, 0, nullptr, 0);
    }
}